// round 1
// baseline (speedup 1.0000x reference)
#include <cuda_runtime.h>

// ---------------------------------------------------------------------------
// Problem constants
// ---------------------------------------------------------------------------
#define NB   16384      // batch
#define NL   16         // hash levels
#define NT   16384      // table size per level
#define NF   2          // features per entry

// Output float offsets
#define SELF_W    608
#define TM_BASE   9961472
#define OP_BASE   15204352
#define OL_BASE   21495808
#define MASK_BASE 27787264
#define AMAP_BASE 27885568
#define UMAP_BASE 44662784

// floor(16 * (2^0.4)^l) for l in 0..15 (verified against float64 reference math)
__constant__ float c_res[16] = {16.f, 21.f, 27.f, 36.f, 48.f, 64.f, 84.f, 111.f,
                                147.f, 194.f, 256.f, 337.f, 445.f, 588.f, 776.f, 1024.f};

__device__ __forceinline__ float lrelu(float x) { return x >= 0.f ? x : 0.01f * x; }

// ---------------------------------------------------------------------------
// Hash-grid encode + fused concat of the adjacent feature vectors.
// Block = 256 points (one thread per point), loop over 16 levels so the
// per-level 128KB table slab stays L1-hot. Encoded 32 floats accumulate in
// padded smem; a coalesced write phase emits [enc | aux_vec] rows.
// Point segments: [0,16384) self | [16384,98304) teammates(5/B)
//                 [98304,196608) opponents(6/B) | [196608,294912) opp_last(6/B)
// All segment boundaries are multiples of 256 -> each block is single-segment.
// ---------------------------------------------------------------------------
__global__ void __launch_bounds__(256)
hash_kernel(const float* __restrict__ self_pos,
            const float* __restrict__ tm_pos,
            const float* __restrict__ op_pos,
            const float* __restrict__ ol_pos,
            const float* __restrict__ self_vec,
            const float* __restrict__ teammates,
            const float* __restrict__ opponents,
            const float* __restrict__ ol_known,
            const float2* __restrict__ table,
            float* __restrict__ out)
{
    __shared__ float enc[256 * 33];   // stride 33 -> conflict-free
    const int t   = threadIdx.x;
    const int blk = blockIdx.x;
    const int gp  = blk * 256 + t;

    int seg, q;
    const float* pos;
    if (gp < 16384)        { seg = 0; q = gp;          pos = self_pos + q * 3; }
    else if (gp < 98304)   { seg = 1; q = gp - 16384;  pos = tm_pos   + q * 3; }
    else if (gp < 196608)  { seg = 2; q = gp - 98304;  pos = op_pos   + q * 3; }
    else                   { seg = 3; q = gp - 196608; pos = ol_pos   + q * 3; }

    const float x0 = __ldg(pos + 0), x1p = __ldg(pos + 1), x2p = __ldg(pos + 2);
    const float xn0 = fminf(fmaxf((x0  + 1.f) * 0.5f, 0.f), 1.f);
    const float xn1 = fminf(fmaxf((x1p + 1.f) * 0.5f, 0.f), 1.f);
    const float xn2 = fminf(fmaxf((x2p + 1.f) * 0.5f, 0.f), 1.f);

    #pragma unroll 4
    for (int l = 0; l < NL; l++) {
        const float r = c_res[l];
        const float s0 = xn0 * r, s1 = xn1 * r, s2 = xn2 * r;
        const float f0 = floorf(s0), f1 = floorf(s1), f2 = floorf(s2);
        const float w0 = s0 - f0, w1 = s1 - f1, w2 = s2 - f2;
        const unsigned c0 = (unsigned)f0, c1 = (unsigned)f1, c2 = (unsigned)f2;

        const unsigned h1a = c1 * 2654435761u;
        const unsigned h1b = h1a + 2654435761u;
        const unsigned h2a = c2 * 805459861u;
        const unsigned h2b = h2a + 805459861u;

        const float2* tl = table + (size_t)l * NT;
        float a0 = 0.f, a1 = 0.f;

        #pragma unroll
        for (int oc = 0; oc < 8; oc++) {
            const int ox = (oc >> 2) & 1, oy = (oc >> 1) & 1, oz = oc & 1;
            const unsigned cc0 = c0 + (unsigned)ox;
            const unsigned hh1 = oy ? h1b : h1a;
            const unsigned hh2 = oz ? h2b : h2a;
            const unsigned idx = (cc0 ^ hh1 ^ hh2) & (NT - 1);
            const float wt = (ox ? w0 : 1.f - w0) *
                             (oy ? w1 : 1.f - w1) *
                             (oz ? w2 : 1.f - w2);
            const float2 f = __ldg(tl + idx);
            a0 = fmaf(wt, f.x, a0);
            a1 = fmaf(wt, f.y, a1);
        }
        enc[t * 33 + 2 * l]     = a0;
        enc[t * 33 + 2 * l + 1] = a1;
    }
    __syncthreads();

    // Coalesced write phase: 32 enc floats + fused aux vector per point.
    if (seg == 0) {
        const int q0 = blk * 256;                       // first self row of block
        for (int i = t; i < 256 * 96; i += 256) {
            const int p = i / 96;
            const int c = i - p * 96;
            const int qq = q0 + p;
            float v = (c < 32) ? enc[p * 33 + c]
                               : __ldg(self_vec + qq * 64 + (c - 32));
            out[qq * SELF_W + c] = v;
        }
    } else {
        const float* aux = (seg == 1) ? teammates : (seg == 2 ? opponents : ol_known);
        const int base   = (seg == 1) ? TM_BASE   : (seg == 2 ? OP_BASE   : OL_BASE);
        const int seg0   = (seg == 1) ? 16384     : (seg == 2 ? 98304     : 196608);
        const int q0     = blk * 256 - seg0;
        for (int i = t; i < 256 * 64; i += 256) {
            const int p = i >> 6;
            const int c = i & 63;
            const int qq = q0 + p;
            float v = (c < 32) ? enc[p * 33 + c]
                               : __ldg(aux + qq * 32 + (c - 32));
            out[base + qq * 64 + c] = v;
        }
    }
}

// ---------------------------------------------------------------------------
// Lidar conv stack: (B,4,128,2)->(B,128,8) -> conv(k3,s2)x3 -> LN -> lrelu.
// One block per batch element, both lidars (q=0 fwd, q=1 rear).
// All convs: out[o] = sum_{j,ci} x[2o+j][ci] * w[(j*CI+ci)*16+co] (pad lo=0,hi=1)
// ---------------------------------------------------------------------------
struct LidarParams {
    const float* lidar;
    const float* w1; const float* b1;
    const float* w2; const float* b2;
    const float* w3; const float* b3;
    const float* g;  const float* be;
};

__global__ void __launch_bounds__(128)
lidar_kernel(LidarParams fp, LidarParams rp, float* __restrict__ out)
{
    __shared__ float w1s[2][384], b1s[2][16];
    __shared__ float w2s[2][768], b2s[2][16];
    __shared__ float w3s[2][768], b3s[2][16];
    __shared__ float gs[2][256], bes[2][256];
    __shared__ float x1s[2][64][17];
    __shared__ float x2s[2][32][17];
    __shared__ float x3s[2][256];
    __shared__ float red[2][2][2];

    const int t = threadIdx.x;
    const int b = blockIdx.x;

    // stage weights
    {
        const LidarParams* P[2] = { &fp, &rp };
        #pragma unroll
        for (int qq = 0; qq < 2; qq++) {
            for (int i = t; i < 384; i += 128) w1s[qq][i] = __ldg(P[qq]->w1 + i);
            for (int i = t; i < 768; i += 128) w2s[qq][i] = __ldg(P[qq]->w2 + i);
            for (int i = t; i < 768; i += 128) w3s[qq][i] = __ldg(P[qq]->w3 + i);
            for (int i = t; i < 256; i += 128) gs[qq][i]  = __ldg(P[qq]->g + i);
            for (int i = t; i < 256; i += 128) bes[qq][i] = __ldg(P[qq]->be + i);
            if (t < 16) {
                b1s[qq][t] = __ldg(P[qq]->b1 + t);
                b2s[qq][t] = __ldg(P[qq]->b2 + t);
                b3s[qq][t] = __ldg(P[qq]->b3 + t);
            }
        }
    }
    __syncthreads();

    // conv1: 128 items = (2 lidars x 64 out positions); in: global lidar
    {
        const int q = t >> 6, o = t & 63;
        const float* lid = (q ? rp.lidar : fp.lidar) + (size_t)b * 1024;
        float xr[24];
        #pragma unroll
        for (int j = 0; j < 3; j++) {
            const int p2 = 2 * o + j;
            #pragma unroll
            for (int c = 0; c < 8; c++) {
                // channel c = a*2+r: offset a*256 + p*2 + r
                xr[j * 8 + c] = (p2 < 128)
                    ? __ldg(lid + (c >> 1) * 256 + p2 * 2 + (c & 1)) : 0.f;
            }
        }
        #pragma unroll
        for (int co = 0; co < 16; co++) {
            float acc = b1s[q][co];
            #pragma unroll
            for (int k = 0; k < 24; k++) acc = fmaf(xr[k], w1s[q][k * 16 + co], acc);
            x1s[q][o][co] = lrelu(acc);
        }
    }
    __syncthreads();

    // conv2: 64 items = (2 x 32)
    if (t < 64) {
        const int q = t >> 5, o = t & 31;
        float xr[48];
        #pragma unroll
        for (int j = 0; j < 3; j++) {
            const int p2 = 2 * o + j;
            #pragma unroll
            for (int ci = 0; ci < 16; ci++)
                xr[j * 16 + ci] = (p2 < 64) ? x1s[q][p2][ci] : 0.f;
        }
        #pragma unroll
        for (int co = 0; co < 16; co++) {
            float acc = b2s[q][co];
            #pragma unroll
            for (int k = 0; k < 48; k++) acc = fmaf(xr[k], w2s[q][k * 16 + co], acc);
            x2s[q][o][co] = lrelu(acc);
        }
    }
    __syncthreads();

    // conv3: 32 items = (2 x 16), no activation
    if (t < 32) {
        const int q = t >> 4, o = t & 15;
        float xr[48];
        #pragma unroll
        for (int j = 0; j < 3; j++) {
            const int p2 = 2 * o + j;
            #pragma unroll
            for (int ci = 0; ci < 16; ci++)
                xr[j * 16 + ci] = (p2 < 32) ? x2s[q][p2][ci] : 0.f;
        }
        #pragma unroll
        for (int co = 0; co < 16; co++) {
            float acc = b3s[q][co];
            #pragma unroll
            for (int k = 0; k < 48; k++) acc = fmaf(xr[k], w3s[q][k * 16 + co], acc);
            x3s[q][o * 16 + co] = acc;
        }
    }
    __syncthreads();

    // LayerNorm over 256 + lrelu; 64 threads per lidar (2 warps each)
    {
        const int q = t >> 6, u = t & 63;
        float v[4];
        #pragma unroll
        for (int i = 0; i < 4; i++) v[i] = x3s[q][u + 64 * i];
        float s  = v[0] + v[1] + v[2] + v[3];
        float ss = v[0] * v[0] + v[1] * v[1] + v[2] * v[2] + v[3] * v[3];
        #pragma unroll
        for (int off = 16; off; off >>= 1) {
            s  += __shfl_xor_sync(0xffffffffu, s,  off);
            ss += __shfl_xor_sync(0xffffffffu, ss, off);
        }
        const int wid2 = (t >> 5) & 1;
        if ((t & 31) == 0) { red[q][wid2][0] = s; red[q][wid2][1] = ss; }
        __syncthreads();
        const float st  = red[q][0][0] + red[q][1][0];
        const float sst = red[q][0][1] + red[q][1][1];
        const float mu  = st * (1.f / 256.f);
        const float var = sst * (1.f / 256.f) - mu * mu;
        const float rstd = rsqrtf(var + 1e-6f);
        float* ob = out + (size_t)b * SELF_W + 96 + q * 256;
        #pragma unroll
        for (int i = 0; i < 4; i++) {
            const int idx = u + 64 * i;
            const float y = (v[i] - mu) * rstd * gs[q][idx] + bes[q][idx];
            ob[idx] = lrelu(y);
        }
    }
}

// ---------------------------------------------------------------------------
// Launch
// ---------------------------------------------------------------------------
extern "C" void kernel_launch(void* const* d_in, const int* in_sizes, int n_in,
                              void* d_out, int out_size)
{
    (void)in_sizes; (void)n_in; (void)out_size;
    float* out = (float*)d_out;

    hash_kernel<<<1152, 256>>>(
        (const float*)d_in[0],        // self_pos
        (const float*)d_in[1],        // teammate_positions
        (const float*)d_in[2],        // opponent_positions
        (const float*)d_in[3],        // opponent_last_positions
        (const float*)d_in[4],        // self_vec
        (const float*)d_in[7],        // teammates
        (const float*)d_in[8],        // opponents
        (const float*)d_in[9],        // opponents_last_known
        (const float2*)d_in[13],      // hash_table
        out);

    LidarParams fp = {
        (const float*)d_in[5],
        (const float*)d_in[14], (const float*)d_in[15],
        (const float*)d_in[16], (const float*)d_in[17],
        (const float*)d_in[18], (const float*)d_in[19],
        (const float*)d_in[20], (const float*)d_in[21]
    };
    LidarParams rp = {
        (const float*)d_in[6],
        (const float*)d_in[22], (const float*)d_in[23],
        (const float*)d_in[24], (const float*)d_in[25],
        (const float*)d_in[26], (const float*)d_in[27],
        (const float*)d_in[28], (const float*)d_in[29]
    };
    lidar_kernel<<<NB, 128>>>(fp, rp, out);

    cudaMemcpyAsync(out + MASK_BASE, d_in[10], 98304u * sizeof(float),
                    cudaMemcpyDeviceToDevice, 0);
    cudaMemcpyAsync(out + AMAP_BASE, d_in[11], 16777216u * sizeof(float),
                    cudaMemcpyDeviceToDevice, 0);
    cudaMemcpyAsync(out + UMAP_BASE, d_in[12], 16777216u * sizeof(float),
                    cudaMemcpyDeviceToDevice, 0);
}

// round 2
// speedup vs baseline: 1.3742x; 1.3742x over previous
#include <cuda_runtime.h>

// ---------------------------------------------------------------------------
// Problem constants
// ---------------------------------------------------------------------------
#define NB   16384      // batch
#define NL   16         // hash levels
#define NT   16384      // table size per level

// Output float offsets
#define SELF_W    608
#define TM_BASE   9961472
#define OP_BASE   15204352
#define OL_BASE   21495808
#define MASK_BASE 27787264
#define AMAP_BASE 27885568
#define UMAP_BASE 44662784

// floor(16 * (2^0.4)^l) for l in 0..15
__constant__ float c_res[16] = {16.f, 21.f, 27.f, 36.f, 48.f, 64.f, 84.f, 111.f,
                                147.f, 194.f, 256.f, 337.f, 445.f, 588.f, 776.f, 1024.f};

__device__ __forceinline__ float lrelu(float x) { return x >= 0.f ? x : 0.01f * x; }

typedef unsigned long long u64;

// packed f32x2 fma: d = a*b + c on both lanes (two independent fp32 FMAs)
__device__ __forceinline__ u64 fma2(u64 a, u64 b, u64 c) {
    u64 d;
    asm("fma.rn.f32x2 %0, %1, %2, %3;" : "=l"(d) : "l"(a), "l"(b), "l"(c));
    return d;
}
__device__ __forceinline__ float2 unpk(u64 v) {
    float x, y;
    asm("mov.b64 {%0,%1}, %2;" : "=f"(x), "=f"(y) : "l"(v));
    return make_float2(x, y);
}

// ---------------------------------------------------------------------------
// Hash-grid encode + fused concat (unchanged from round 1; passes).
// ---------------------------------------------------------------------------
__global__ void __launch_bounds__(256)
hash_kernel(const float* __restrict__ self_pos,
            const float* __restrict__ tm_pos,
            const float* __restrict__ op_pos,
            const float* __restrict__ ol_pos,
            const float* __restrict__ self_vec,
            const float* __restrict__ teammates,
            const float* __restrict__ opponents,
            const float* __restrict__ ol_known,
            const float2* __restrict__ table,
            float* __restrict__ out)
{
    __shared__ float enc[256 * 33];
    const int t   = threadIdx.x;
    const int blk = blockIdx.x;
    const int gp  = blk * 256 + t;

    int seg, q;
    const float* pos;
    if (gp < 16384)        { seg = 0; q = gp;          pos = self_pos + q * 3; }
    else if (gp < 98304)   { seg = 1; q = gp - 16384;  pos = tm_pos   + q * 3; }
    else if (gp < 196608)  { seg = 2; q = gp - 98304;  pos = op_pos   + q * 3; }
    else                   { seg = 3; q = gp - 196608; pos = ol_pos   + q * 3; }

    const float x0 = __ldg(pos + 0), x1p = __ldg(pos + 1), x2p = __ldg(pos + 2);
    const float xn0 = fminf(fmaxf((x0  + 1.f) * 0.5f, 0.f), 1.f);
    const float xn1 = fminf(fmaxf((x1p + 1.f) * 0.5f, 0.f), 1.f);
    const float xn2 = fminf(fmaxf((x2p + 1.f) * 0.5f, 0.f), 1.f);

    #pragma unroll 4
    for (int l = 0; l < NL; l++) {
        const float r = c_res[l];
        const float s0 = xn0 * r, s1 = xn1 * r, s2 = xn2 * r;
        const float f0 = floorf(s0), f1 = floorf(s1), f2 = floorf(s2);
        const float w0 = s0 - f0, w1 = s1 - f1, w2 = s2 - f2;
        const unsigned c0 = (unsigned)f0, c1 = (unsigned)f1, c2 = (unsigned)f2;

        const unsigned h1a = c1 * 2654435761u;
        const unsigned h1b = h1a + 2654435761u;
        const unsigned h2a = c2 * 805459861u;
        const unsigned h2b = h2a + 805459861u;

        const float2* tl = table + (size_t)l * NT;
        float a0 = 0.f, a1 = 0.f;

        #pragma unroll
        for (int oc = 0; oc < 8; oc++) {
            const int ox = (oc >> 2) & 1, oy = (oc >> 1) & 1, oz = oc & 1;
            const unsigned cc0 = c0 + (unsigned)ox;
            const unsigned hh1 = oy ? h1b : h1a;
            const unsigned hh2 = oz ? h2b : h2a;
            const unsigned idx = (cc0 ^ hh1 ^ hh2) & (NT - 1);
            const float wt = (ox ? w0 : 1.f - w0) *
                             (oy ? w1 : 1.f - w1) *
                             (oz ? w2 : 1.f - w2);
            const float2 f = __ldg(tl + idx);
            a0 = fmaf(wt, f.x, a0);
            a1 = fmaf(wt, f.y, a1);
        }
        enc[t * 33 + 2 * l]     = a0;
        enc[t * 33 + 2 * l + 1] = a1;
    }
    __syncthreads();

    if (seg == 0) {
        const int q0 = blk * 256;
        for (int i = t; i < 256 * 96; i += 256) {
            const int p = i / 96;
            const int c = i - p * 96;
            const int qq = q0 + p;
            float v = (c < 32) ? enc[p * 33 + c]
                               : __ldg(self_vec + qq * 64 + (c - 32));
            out[qq * SELF_W + c] = v;
        }
    } else {
        const float* aux = (seg == 1) ? teammates : (seg == 2 ? opponents : ol_known);
        const int base   = (seg == 1) ? TM_BASE   : (seg == 2 ? OP_BASE   : OL_BASE);
        const int seg0   = (seg == 1) ? 16384     : (seg == 2 ? 98304     : 196608);
        const int q0     = blk * 256 - seg0;
        for (int i = t; i < 256 * 64; i += 256) {
            const int p = i >> 6;
            const int c = i & 63;
            const int qq = q0 + p;
            float v = (c < 32) ? enc[p * 33 + c]
                               : __ldg(aux + qq * 32 + (c - 32));
            out[base + qq * 64 + c] = v;
        }
    }
}

// ---------------------------------------------------------------------------
// Lidar: weight pre-transpose into k-major layout (one tiny kernel).
// g_wT layout (floats):
//   [0,    768): wT1[q][co][k24]   (k = j*8  + c,  c = a*2+r)
//   [768, 2304): wT2[q][co][k48]   (k = j*16 + ci)
//   [2304,3840): wT3[q][co][k48]
// ---------------------------------------------------------------------------
__device__ __align__(16) float g_wT[3840];

__global__ void prep_kernel(const float* __restrict__ fw1, const float* __restrict__ fw2,
                            const float* __restrict__ fw3, const float* __restrict__ rw1,
                            const float* __restrict__ rw2, const float* __restrict__ rw3)
{
    int i = blockIdx.x * blockDim.x + threadIdx.x;
    if (i < 768) {
        int q = i / 384, r = i % 384, co = r / 24, k = r % 24;
        const float* w = q ? rw1 : fw1;
        g_wT[i] = w[k * 16 + co];
    } else if (i < 2304) {
        int j = i - 768, q = j / 768, r = j % 768, co = r / 48, k = r % 48;
        const float* w = q ? rw2 : fw2;
        g_wT[i] = w[k * 16 + co];
    } else if (i < 3840) {
        int j = i - 2304, q = j / 768, r = j % 768, co = r / 48, k = r % 48;
        const float* w = q ? rw3 : fw3;
        g_wT[i] = w[k * 16 + co];
    }
}

// ---------------------------------------------------------------------------
// Lidar conv stack, f32x2 even/odd-k accumulation.
// Block = 128 threads, NBATCH=4 batches per block. All phases use all threads.
// smem (floats): [0,3840) weights | X1 [3840,6400): x1 [2][64][20]
//                X2 [6400,7680): x2 [2][32][20] | X3 [7680,8192): x3 [2][256]
//                RED [8192,8200)
// ---------------------------------------------------------------------------
#define X1OFF 3840
#define X2OFF 6400
#define X3OFF 7680
#define REDOF 8192
#define NBATCH 4

__global__ void __launch_bounds__(128)
lidar_kernel(const float* __restrict__ fl_in, const float* __restrict__ rl_in,
             const float* __restrict__ fb1, const float* __restrict__ fb2,
             const float* __restrict__ fb3, const float* __restrict__ rb1,
             const float* __restrict__ rb2, const float* __restrict__ rb3,
             const float* __restrict__ fg, const float* __restrict__ fbe,
             const float* __restrict__ rg, const float* __restrict__ rbe,
             float* __restrict__ out)
{
    __shared__ __align__(16) float sm[8200];
    const int t = threadIdx.x;

    // stage transposed weights (960 float4)
    {
        const float4* src = (const float4*)g_wT;
        float4* dst = (float4*)sm;
        for (int i = t; i < 960; i += 128) dst[i] = src[i];
    }
    __syncthreads();

    #pragma unroll 1
    for (int it = 0; it < NBATCH; ++it) {
        const int b = blockIdx.x * NBATCH + it;

        // ---- conv1: thread = (q, o) ; 64 positions x 16 co per lidar ----
        {
            const int q = t >> 6, o = t & 63;
            const float* lid = (q ? rl_in : fl_in) + (size_t)b * 1024;
            u64 xp[12];   // k-pairs: pair p = j*4+a -> (x[k=2p], x[k=2p+1]) = (r0,r1) of antenna a
            #pragma unroll
            for (int j = 0; j < 3; j++) {
                const int p2 = 2 * o + j;
                const bool ok = p2 < 128;
                #pragma unroll
                for (int a = 0; a < 4; a++)
                    xp[j * 4 + a] = ok ? *(const u64*)(lid + a * 256 + p2 * 2) : 0ull;
            }
            const float* bp = q ? rb1 : fb1;
            float yv[16];
            #pragma unroll
            for (int co = 0; co < 16; co++) {
                const u64* wr = ((const u64*)sm) + q * 192 + co * 12;
                u64 acc = 0ull;
                #pragma unroll
                for (int p = 0; p < 12; p++) acc = fma2(xp[p], wr[p], acc);
                float2 ab = unpk(acc);
                yv[co] = lrelu(__ldg(bp + co) + (ab.x + ab.y));
            }
            float* xw = sm + X1OFF + (q * 64 + o) * 20;
            #pragma unroll
            for (int v = 0; v < 4; v++)
                *(float4*)(xw + 4 * v) = make_float4(yv[4*v], yv[4*v+1], yv[4*v+2], yv[4*v+3]);
        }
        __syncthreads();

        // ---- conv2: thread = (q, half, o) ; 32 positions x 8 co ----
        {
            const int q = t >> 6, rem = t & 63, h = rem >> 5, o = rem & 31;
            u64 xp[24];
            #pragma unroll
            for (int j = 0; j < 3; j++) {
                const int p2 = 2 * o + j;
                const bool ok = p2 < 64;
                const ulonglong2* src = (const ulonglong2*)(sm + X1OFF + (q * 64 + p2) * 20);
                #pragma unroll
                for (int v = 0; v < 4; v++) {
                    ulonglong2 u = ok ? src[v] : make_ulonglong2(0ull, 0ull);
                    xp[j * 8 + 2 * v]     = u.x;
                    xp[j * 8 + 2 * v + 1] = u.y;
                }
            }
            const float* bp = q ? rb2 : fb2;
            float yv[8];
            #pragma unroll
            for (int ci = 0; ci < 8; ci++) {
                const int co = h * 8 + ci;
                const u64* wr = ((const u64*)sm) + 384 + q * 384 + co * 24;
                u64 acc = 0ull;
                #pragma unroll
                for (int p = 0; p < 24; p++) acc = fma2(xp[p], wr[p], acc);
                float2 ab = unpk(acc);
                yv[ci] = lrelu(__ldg(bp + co) + (ab.x + ab.y));
            }
            float* xw = sm + X2OFF + (q * 32 + o) * 20 + h * 8;
            *(float4*)xw       = make_float4(yv[0], yv[1], yv[2], yv[3]);
            *(float4*)(xw + 4) = make_float4(yv[4], yv[5], yv[6], yv[7]);
        }
        __syncthreads();

        // ---- conv3: thread = (q, quarter, o) ; 16 positions x 4 co, no act ----
        {
            const int q = t >> 6, rem = t & 63, o = rem & 15, qr = rem >> 4;
            u64 xp[24];
            #pragma unroll
            for (int j = 0; j < 3; j++) {
                const int p2 = 2 * o + j;
                const bool ok = p2 < 32;
                const ulonglong2* src = (const ulonglong2*)(sm + X2OFF + (q * 32 + p2) * 20);
                #pragma unroll
                for (int v = 0; v < 4; v++) {
                    ulonglong2 u = ok ? src[v] : make_ulonglong2(0ull, 0ull);
                    xp[j * 8 + 2 * v]     = u.x;
                    xp[j * 8 + 2 * v + 1] = u.y;
                }
            }
            const float* bp = q ? rb3 : fb3;
            float yv[4];
            #pragma unroll
            for (int ci = 0; ci < 4; ci++) {
                const int co = qr * 4 + ci;
                const u64* wr = ((const u64*)sm) + 1152 + q * 384 + co * 24;
                u64 acc = 0ull;
                #pragma unroll
                for (int p = 0; p < 24; p++) acc = fma2(xp[p], wr[p], acc);
                float2 ab = unpk(acc);
                yv[ci] = __ldg(bp + co) + (ab.x + ab.y);
            }
            *(float4*)(sm + X3OFF + q * 256 + o * 16 + qr * 4)
                = make_float4(yv[0], yv[1], yv[2], yv[3]);
        }
        __syncthreads();

        // ---- LayerNorm(256) + lrelu ; 64 threads (2 warps) per lidar ----
        {
            const int q = t >> 6, u = t & 63;
            float v[4];
            #pragma unroll
            for (int i = 0; i < 4; i++) v[i] = sm[X3OFF + q * 256 + u + 64 * i];
            float s  = v[0] + v[1] + v[2] + v[3];
            float ss = v[0]*v[0] + v[1]*v[1] + v[2]*v[2] + v[3]*v[3];
            #pragma unroll
            for (int off = 16; off; off >>= 1) {
                s  += __shfl_xor_sync(0xffffffffu, s,  off);
                ss += __shfl_xor_sync(0xffffffffu, ss, off);
            }
            const int w2 = (t >> 5) & 1;
            if ((t & 31) == 0) { sm[REDOF + q*4 + w2*2] = s; sm[REDOF + q*4 + w2*2 + 1] = ss; }
            __syncthreads();
            const float st  = sm[REDOF + q*4] + sm[REDOF + q*4 + 2];
            const float sst = sm[REDOF + q*4 + 1] + sm[REDOF + q*4 + 3];
            const float mu  = st * (1.f / 256.f);
            const float var = sst * (1.f / 256.f) - mu * mu;
            const float rstd = rsqrtf(var + 1e-6f);
            const float* gp  = q ? rg  : fg;
            const float* bep = q ? rbe : fbe;
            float* ob = out + (size_t)b * SELF_W + 96 + q * 256;
            #pragma unroll
            for (int i = 0; i < 4; i++) {
                const int idx = u + 64 * i;
                const float y = (v[i] - mu) * rstd * __ldg(gp + idx) + __ldg(bep + idx);
                ob[idx] = lrelu(y);
            }
        }
        // next iteration's conv1 writes x1s only; all readers of x1s (conv2)
        // are behind the conv2-end barrier of this iteration -> safe.
    }
}

// ---------------------------------------------------------------------------
// Launch
// ---------------------------------------------------------------------------
extern "C" void kernel_launch(void* const* d_in, const int* in_sizes, int n_in,
                              void* d_out, int out_size)
{
    (void)in_sizes; (void)n_in; (void)out_size;
    float* out = (float*)d_out;

    prep_kernel<<<8, 512>>>(
        (const float*)d_in[14], (const float*)d_in[16], (const float*)d_in[18],
        (const float*)d_in[22], (const float*)d_in[24], (const float*)d_in[26]);

    hash_kernel<<<1152, 256>>>(
        (const float*)d_in[0],        // self_pos
        (const float*)d_in[1],        // teammate_positions
        (const float*)d_in[2],        // opponent_positions
        (const float*)d_in[3],        // opponent_last_positions
        (const float*)d_in[4],        // self_vec
        (const float*)d_in[7],        // teammates
        (const float*)d_in[8],        // opponents
        (const float*)d_in[9],        // opponents_last_known
        (const float2*)d_in[13],      // hash_table
        out);

    lidar_kernel<<<NB / NBATCH, 128>>>(
        (const float*)d_in[5],  (const float*)d_in[6],
        (const float*)d_in[15], (const float*)d_in[17], (const float*)d_in[19],
        (const float*)d_in[23], (const float*)d_in[25], (const float*)d_in[27],
        (const float*)d_in[20], (const float*)d_in[21],
        (const float*)d_in[28], (const float*)d_in[29],
        out);

    cudaMemcpyAsync(out + MASK_BASE, d_in[10], 98304u * sizeof(float),
                    cudaMemcpyDeviceToDevice, 0);
    cudaMemcpyAsync(out + AMAP_BASE, d_in[11], 16777216u * sizeof(float),
                    cudaMemcpyDeviceToDevice, 0);
    cudaMemcpyAsync(out + UMAP_BASE, d_in[12], 16777216u * sizeof(float),
                    cudaMemcpyDeviceToDevice, 0);
}

// round 4
// speedup vs baseline: 1.8903x; 1.3756x over previous
#include <cuda_runtime.h>

// ---------------------------------------------------------------------------
// Problem constants
// ---------------------------------------------------------------------------
#define NB   16384
#define NL   16
#define NT   16384

// Output float offsets
#define SELF_W    608
#define TM_BASE   9961472
#define OP_BASE   15204352
#define OL_BASE   21495808
#define MASK_BASE 27787264
#define AMAP_BASE 27885568
#define UMAP_BASE 44662784

// Block striping: period 33 = 9 hash + 16 lidar + 8 copy; 128 periods
#define GRID_BLKS 4224
#define SMEM_FLOATS 12560        // lidar: 3840 weights + 2 * 4360 activations
#define SMEM_BYTES (SMEM_FLOATS * 4)

__constant__ float c_res[16] = {16.f, 21.f, 27.f, 36.f, 48.f, 64.f, 84.f, 111.f,
                                147.f, 194.f, 256.f, 337.f, 445.f, 588.f, 776.f, 1024.f};

__device__ __forceinline__ float lrelu(float x) { return x >= 0.f ? x : 0.01f * x; }

typedef unsigned long long u64;

__device__ __forceinline__ u64 fma2(u64 a, u64 b, u64 c) {
    u64 d;
    asm("fma.rn.f32x2 %0, %1, %2, %3;" : "=l"(d) : "l"(a), "l"(b), "l"(c));
    return d;
}
__device__ __forceinline__ float2 unpk(u64 v) {
    float x, y;
    asm("mov.b64 {%0,%1}, %2;" : "=f"(x), "=f"(y) : "l"(v));
    return make_float2(x, y);
}

struct Args {
    const float* p[30];
    float* out;
};

// ---------------------------------------------------------------------------
// Hash part: block of 256 points, identical math to the passing round-1/2 code.
// ---------------------------------------------------------------------------
__device__ __forceinline__ void hash_part(int blk, const Args& A, float* sm)
{
    float* enc = sm;                       // 256*33 = 8448 floats
    const int t  = threadIdx.x;
    const int gp = blk * 256 + t;

    int seg, q;
    const float* pos;
    if (gp < 16384)        { seg = 0; q = gp;          pos = A.p[0] + q * 3; }
    else if (gp < 98304)   { seg = 1; q = gp - 16384;  pos = A.p[1] + q * 3; }
    else if (gp < 196608)  { seg = 2; q = gp - 98304;  pos = A.p[2] + q * 3; }
    else                   { seg = 3; q = gp - 196608; pos = A.p[3] + q * 3; }

    const float2* table = (const float2*)A.p[13];

    const float x0 = __ldg(pos + 0), x1p = __ldg(pos + 1), x2p = __ldg(pos + 2);
    const float xn0 = fminf(fmaxf((x0  + 1.f) * 0.5f, 0.f), 1.f);
    const float xn1 = fminf(fmaxf((x1p + 1.f) * 0.5f, 0.f), 1.f);
    const float xn2 = fminf(fmaxf((x2p + 1.f) * 0.5f, 0.f), 1.f);

    #pragma unroll 4
    for (int l = 0; l < NL; l++) {
        const float r = c_res[l];
        const float s0 = xn0 * r, s1 = xn1 * r, s2 = xn2 * r;
        const float f0 = floorf(s0), f1 = floorf(s1), f2 = floorf(s2);
        const float w0 = s0 - f0, w1 = s1 - f1, w2 = s2 - f2;
        const unsigned c0 = (unsigned)f0, c1 = (unsigned)f1, c2 = (unsigned)f2;

        const unsigned h1a = c1 * 2654435761u;
        const unsigned h1b = h1a + 2654435761u;
        const unsigned h2a = c2 * 805459861u;
        const unsigned h2b = h2a + 805459861u;

        const float2* tl = table + (size_t)l * NT;
        float a0 = 0.f, a1 = 0.f;

        #pragma unroll
        for (int oc = 0; oc < 8; oc++) {
            const int ox = (oc >> 2) & 1, oy = (oc >> 1) & 1, oz = oc & 1;
            const unsigned cc0 = c0 + (unsigned)ox;
            const unsigned hh1 = oy ? h1b : h1a;
            const unsigned hh2 = oz ? h2b : h2a;
            const unsigned idx = (cc0 ^ hh1 ^ hh2) & (NT - 1);
            const float wt = (ox ? w0 : 1.f - w0) *
                             (oy ? w1 : 1.f - w1) *
                             (oz ? w2 : 1.f - w2);
            const float2 f = __ldg(tl + idx);
            a0 = fmaf(wt, f.x, a0);
            a1 = fmaf(wt, f.y, a1);
        }
        enc[t * 33 + 2 * l]     = a0;
        enc[t * 33 + 2 * l + 1] = a1;
    }
    __syncthreads();

    float* out = A.out;
    if (seg == 0) {
        const float* self_vec = A.p[4];
        const int q0 = blk * 256;
        for (int i = t; i < 256 * 96; i += 256) {
            const int p = i / 96;
            const int c = i - p * 96;
            const int qq = q0 + p;
            float v = (c < 32) ? enc[p * 33 + c]
                               : __ldg(self_vec + qq * 64 + (c - 32));
            out[qq * SELF_W + c] = v;
        }
    } else {
        const float* aux = (seg == 1) ? A.p[7] : (seg == 2 ? A.p[8] : A.p[9]);
        const int base   = (seg == 1) ? TM_BASE : (seg == 2 ? OP_BASE : OL_BASE);
        const int seg0   = (seg == 1) ? 16384   : (seg == 2 ? 98304   : 196608);
        const int q0     = blk * 256 - seg0;
        for (int i = t; i < 256 * 64; i += 256) {
            const int p = i >> 6;
            const int c = i & 63;
            const int qq = q0 + p;
            float v = (c < 32) ? enc[p * 33 + c]
                               : __ldg(aux + qq * 32 + (c - 32));
            out[base + qq * 64 + c] = v;
        }
    }
}

// ---------------------------------------------------------------------------
// Lidar part: 256 threads = 2 batch-lanes x 128; 4 iterations -> 8 batches/block.
// smem: W [0,3840) k-major weights | per-lane XB: X1 2560 | X2 1280 | X3 512 | RED 8
// ---------------------------------------------------------------------------
__device__ __forceinline__ void lidar_part(int lb, const Args& A, float* sm)
{
    const int t = threadIdx.x;
    float* W = sm;

    // stage transposed weights (k-major) straight from global
    for (int i = t; i < 3840; i += 256) {
        float v;
        if (i < 768) {
            int q = i / 384, r = i % 384, co = r / 24, k = r % 24;
            v = __ldg((q ? A.p[22] : A.p[14]) + k * 16 + co);
        } else if (i < 2304) {
            int j = i - 768, q = j / 768, r = j % 768, co = r / 48, k = r % 48;
            v = __ldg((q ? A.p[24] : A.p[16]) + k * 16 + co);
        } else {
            int j = i - 2304, q = j / 768, r = j % 768, co = r / 48, k = r % 48;
            v = __ldg((q ? A.p[26] : A.p[18]) + k * 16 + co);
        }
        W[i] = v;
    }
    __syncthreads();

    const int s = t >> 7;          // batch lane
    const int l = t & 127;
    float* XB  = sm + 3840 + s * 4360;
    float* X1  = XB;               // [2][64][20]
    float* X2  = XB + 2560;        // [2][32][20]
    float* X3  = XB + 3840;        // [2][256]
    float* RED = XB + 4352;        // [2][4]

    const float* fl_in = A.p[5];
    const float* rl_in = A.p[6];
    float* out = A.out;

    #pragma unroll 1
    for (int it = 0; it < 4; ++it) {
        const int b = lb * 8 + it * 2 + s;

        // ---- conv1 ----
        {
            const int q = l >> 6, o = l & 63;
            const float* lid = (q ? rl_in : fl_in) + (size_t)b * 1024;
            u64 xp[12];
            #pragma unroll
            for (int j = 0; j < 3; j++) {
                const int p2 = 2 * o + j;
                const bool ok = p2 < 128;
                #pragma unroll
                for (int a = 0; a < 4; a++)
                    xp[j * 4 + a] = ok ? *(const u64*)(lid + a * 256 + p2 * 2) : 0ull;
            }
            const float* bp = q ? A.p[23] : A.p[15];
            float yv[16];
            #pragma unroll
            for (int co = 0; co < 16; co++) {
                const u64* wr = ((const u64*)W) + q * 192 + co * 12;
                u64 acc = 0ull;
                #pragma unroll
                for (int p = 0; p < 12; p++) acc = fma2(xp[p], wr[p], acc);
                float2 ab = unpk(acc);
                yv[co] = lrelu(__ldg(bp + co) + (ab.x + ab.y));
            }
            float* xw = X1 + (q * 64 + o) * 20;
            #pragma unroll
            for (int v = 0; v < 4; v++)
                *(float4*)(xw + 4 * v) = make_float4(yv[4*v], yv[4*v+1], yv[4*v+2], yv[4*v+3]);
        }
        __syncthreads();

        // ---- conv2 ----
        {
            const int q = l >> 6, rem = l & 63, h = rem >> 5, o = rem & 31;
            u64 xp[24];
            #pragma unroll
            for (int j = 0; j < 3; j++) {
                const int p2 = 2 * o + j;
                const bool ok = p2 < 64;
                const ulonglong2* src = (const ulonglong2*)(X1 + (q * 64 + p2) * 20);
                #pragma unroll
                for (int v = 0; v < 4; v++) {
                    ulonglong2 u = ok ? src[v] : make_ulonglong2(0ull, 0ull);
                    xp[j * 8 + 2 * v]     = u.x;
                    xp[j * 8 + 2 * v + 1] = u.y;
                }
            }
            const float* bp = q ? A.p[25] : A.p[17];
            float yv[8];
            #pragma unroll
            for (int ci = 0; ci < 8; ci++) {
                const int co = h * 8 + ci;
                const u64* wr = ((const u64*)W) + 384 + q * 384 + co * 24;
                u64 acc = 0ull;
                #pragma unroll
                for (int p = 0; p < 24; p++) acc = fma2(xp[p], wr[p], acc);
                float2 ab = unpk(acc);
                yv[ci] = lrelu(__ldg(bp + co) + (ab.x + ab.y));
            }
            float* xw = X2 + (q * 32 + o) * 20 + h * 8;
            *(float4*)xw       = make_float4(yv[0], yv[1], yv[2], yv[3]);
            *(float4*)(xw + 4) = make_float4(yv[4], yv[5], yv[6], yv[7]);
        }
        __syncthreads();

        // ---- conv3 (no activation) ----
        {
            const int q = l >> 6, rem = l & 63, o = rem & 15, qr = rem >> 4;
            u64 xp[24];
            #pragma unroll
            for (int j = 0; j < 3; j++) {
                const int p2 = 2 * o + j;
                const bool ok = p2 < 32;
                const ulonglong2* src = (const ulonglong2*)(X2 + (q * 32 + p2) * 20);
                #pragma unroll
                for (int v = 0; v < 4; v++) {
                    ulonglong2 u = ok ? src[v] : make_ulonglong2(0ull, 0ull);
                    xp[j * 8 + 2 * v]     = u.x;
                    xp[j * 8 + 2 * v + 1] = u.y;
                }
            }
            const float* bp = q ? A.p[27] : A.p[19];
            float yv[4];
            #pragma unroll
            for (int ci = 0; ci < 4; ci++) {
                const int co = qr * 4 + ci;
                const u64* wr = ((const u64*)W) + 1152 + q * 384 + co * 24;
                u64 acc = 0ull;
                #pragma unroll
                for (int p = 0; p < 24; p++) acc = fma2(xp[p], wr[p], acc);
                float2 ab = unpk(acc);
                yv[ci] = __ldg(bp + co) + (ab.x + ab.y);
            }
            *(float4*)(X3 + q * 256 + o * 16 + qr * 4)
                = make_float4(yv[0], yv[1], yv[2], yv[3]);
        }
        __syncthreads();

        // ---- LayerNorm(256) + lrelu ----
        {
            const int q = l >> 6, u = l & 63;
            float v[4];
            #pragma unroll
            for (int i = 0; i < 4; i++) v[i] = X3[q * 256 + u + 64 * i];
            float ssum  = v[0] + v[1] + v[2] + v[3];
            float ssq   = v[0]*v[0] + v[1]*v[1] + v[2]*v[2] + v[3]*v[3];
            #pragma unroll
            for (int off = 16; off; off >>= 1) {
                ssum += __shfl_xor_sync(0xffffffffu, ssum, off);
                ssq  += __shfl_xor_sync(0xffffffffu, ssq,  off);
            }
            const int w2 = (l >> 5) & 1;
            if ((l & 31) == 0) { RED[q*4 + w2*2] = ssum; RED[q*4 + w2*2 + 1] = ssq; }
            __syncthreads();
            const float st  = RED[q*4]     + RED[q*4 + 2];
            const float sst = RED[q*4 + 1] + RED[q*4 + 3];
            const float mu  = st * (1.f / 256.f);
            const float var = sst * (1.f / 256.f) - mu * mu;
            const float rstd = rsqrtf(var + 1e-6f);
            const float* gp  = q ? A.p[28] : A.p[20];
            const float* bep = q ? A.p[29] : A.p[21];
            float* ob = out + (size_t)b * SELF_W + 96 + q * 256;
            #pragma unroll
            for (int i = 0; i < 4; i++) {
                const int idx = u + 64 * i;
                const float y = (v[i] - mu) * rstd * __ldg(gp + idx) + __ldg(bep + idx);
                ob[idx] = lrelu(y);
            }
        }
    }
}

// ---------------------------------------------------------------------------
// Copy part: masks + agent_map + unmasked_agent_map as float4, grid-strided
// across the 1024 copy blocks. Totals (float4): 24576 + 4194304 + 4194304.
// ---------------------------------------------------------------------------
__device__ __forceinline__ void copy_part(int cb, const Args& A)
{
    const float4* ms = (const float4*)A.p[10];
    const float4* am = (const float4*)A.p[11];
    const float4* um = (const float4*)A.p[12];
    float4* out = (float4*)A.out;
    const int t = threadIdx.x;
    const int total = 24576 + 4194304 + 4194304;   // 8413184

    for (int i = cb * 256 + t; i < total; i += 1024 * 256) {
        float4 v; int o;
        if (i < 24576) {
            v = __ldg(ms + i);                      o = MASK_BASE / 4 + i;
        } else if (i < 24576 + 4194304) {
            const int j = i - 24576;
            v = __ldg(am + j);                      o = AMAP_BASE / 4 + j;
        } else {
            const int j = i - (24576 + 4194304);
            v = __ldg(um + j);                      o = UMAP_BASE / 4 + j;
        }
        out[o] = v;
    }
}

// ---------------------------------------------------------------------------
// Fused kernel: period-33 block striping (9 hash / 16 lidar / 8 copy).
// ---------------------------------------------------------------------------
__global__ void __launch_bounds__(256)
fused_kernel(Args A)
{
    extern __shared__ float sm[];
    const int b = blockIdx.x;
    const int period = b / 33;
    const int r = b - period * 33;

    if (r < 9) {
        hash_part(period * 9 + r, A, sm);
    } else if (r < 25) {
        lidar_part(period * 16 + (r - 9), A, sm);
    } else {
        copy_part(period * 8 + (r - 25), A);
    }
}

// ---------------------------------------------------------------------------
// Launch
// ---------------------------------------------------------------------------
extern "C" void kernel_launch(void* const* d_in, const int* in_sizes, int n_in,
                              void* d_out, int out_size)
{
    (void)in_sizes; (void)n_in; (void)out_size;

    static bool attr_done = false;
    if (!attr_done) {
        cudaFuncSetAttribute(fused_kernel,
                             cudaFuncAttributeMaxDynamicSharedMemorySize, SMEM_BYTES);
        attr_done = true;
    }

    Args A;
    for (int i = 0; i < 30; i++) A.p[i] = (const float*)d_in[i];
    A.out = (float*)d_out;

    fused_kernel<<<GRID_BLKS, 256, SMEM_BYTES>>>(A);
}